// round 1
// baseline (speedup 1.0000x reference)
#include <cuda_runtime.h>
#include <cstdint>

// ---------------------------------------------------------------------------
// Problem constants
// ---------------------------------------------------------------------------
static constexpr int B_   = 64;
static constexpr int SEQ  = 512;   // W == BLOCK
static constexpr int C_   = 512;   // n_embd
static constexpr int H_   = 8;
static constexpr int DH_  = 64;
static constexpr int MROWS = B_ * SEQ;        // 32768
static constexpr int CTXN  = SEQ * C_;        // 262144 (W_ctx output width)

// ---------------------------------------------------------------------------
// Scratch (allocation-free: __device__ globals)
// ---------------------------------------------------------------------------
__device__ float g_qkv[(long long)MROWS * 3 * C_];   // [32768, 1536]
__device__ float g_attn[(long long)MROWS * C_];      // [32768, 512]  attention out
__device__ float g_ctx[(long long)MROWS * C_];       // [32768, 512]  last@W_ctx

// ---------------------------------------------------------------------------
// Generic fp32 GEMM: C[M,N] = A[M,K] @ B[K,N], all row-major.
// 128x128 tile, BK=8, 8x8 per-thread microkernel, 256 threads.
// FUSE: A element = A[i] + A2[i] (for prev_decomposed + ctx).
// Requires M%128==0, N%128==0, K%8==0 (true for all uses here).
// ---------------------------------------------------------------------------
template <bool FUSE>
__global__ __launch_bounds__(256)
void sgemm128(int M, int N, int K,
              const float* __restrict__ A,
              const float* __restrict__ A2,
              const float* __restrict__ B,
              float* __restrict__ C)
{
    constexpr int BM = 128, BN = 128, BK = 8, TM = 8, TN = 8;
    __shared__ float As[BK][BM];   // A tile, transposed
    __shared__ float Bs[BK][BN];

    const int tid = threadIdx.x;
    const int tx  = tid & 15;          // 0..15 -> 8 output cols each
    const int ty  = tid >> 4;          // 0..15 -> 8 output rows each

    // A tile loads: 128 rows x 8 k = 1024 floats = 256 float4 along K
    const int aRow = tid >> 1;         // 0..127
    const int aCol = (tid & 1) * 4;    // 0 or 4
    // B tile loads: 8 k x 128 cols = 256 float4 along N
    const int bRow = tid >> 5;         // 0..7
    const int bCol = (tid & 31) * 4;   // 0..124

    const size_t aBase = (size_t)(blockIdx.y * BM + aRow) * K + aCol;
    const size_t bBase = (size_t)blockIdx.x * BN + bCol;

    float acc[TM][TN];
#pragma unroll
    for (int i = 0; i < TM; ++i)
#pragma unroll
        for (int j = 0; j < TN; ++j) acc[i][j] = 0.f;

    for (int k0 = 0; k0 < K; k0 += BK) {
        float4 a = *(const float4*)(A + aBase + k0);
        if (FUSE) {
            float4 a2 = *(const float4*)(A2 + aBase + k0);
            a.x += a2.x; a.y += a2.y; a.z += a2.z; a.w += a2.w;
        }
        As[aCol + 0][aRow] = a.x;
        As[aCol + 1][aRow] = a.y;
        As[aCol + 2][aRow] = a.z;
        As[aCol + 3][aRow] = a.w;
        *(float4*)&Bs[bRow][bCol] =
            *(const float4*)(B + (size_t)(k0 + bRow) * N + bBase);
        __syncthreads();

#pragma unroll
        for (int k = 0; k < BK; ++k) {
            float rM[TM], rN[TN];
#pragma unroll
            for (int i = 0; i < TM; ++i) rM[i] = As[k][ty * TM + i];
#pragma unroll
            for (int j = 0; j < TN; ++j) rN[j] = Bs[k][tx * TN + j];
#pragma unroll
            for (int i = 0; i < TM; ++i)
#pragma unroll
                for (int j = 0; j < TN; ++j)
                    acc[i][j] = fmaf(rM[i], rN[j], acc[i][j]);
        }
        __syncthreads();
    }

#pragma unroll
    for (int i = 0; i < TM; ++i) {
        const size_t crow =
            (size_t)(blockIdx.y * BM + ty * TM + i) * N + blockIdx.x * BN + tx * TN;
#pragma unroll
        for (int j = 0; j < TN; j += 4) {
            float4 v = make_float4(acc[i][j], acc[i][j + 1], acc[i][j + 2], acc[i][j + 3]);
            *(float4*)(C + crow + j) = v;
        }
    }
}

// ---------------------------------------------------------------------------
// Fused causal attention. One CTA per (q-block of 64 rows, head, batch).
// 256 threads: thread (r = tid/4, cg = tid%4) owns q-row r, dh cols [cg*16, cg*16+16).
// Q row and P row live in registers distributed across the 4-lane group;
// cross-lane values fetched with __shfl_sync. K stored transposed in smem so
// the S-loop and PV-loop both use vectorized float4 LDS.
// Online softmax (flash style).
// ---------------------------------------------------------------------------
__global__ __launch_bounds__(256)
void attn_kernel(const float* __restrict__ qkv, float* __restrict__ out)
{
    const int qb = blockIdx.x;   // 0..7  (q block)
    const int h  = blockIdx.y;   // 0..7
    const int b  = blockIdx.z;   // 0..63

    __shared__ float KsT[64][68];   // [d][key]   (68 pad: keeps 16B alignment, spreads banks)
    __shared__ float Vs[64][68];    // [key][d]

    const int tid  = threadIdx.x;
    const int r    = tid >> 2;      // 0..63  q row within block
    const int cg   = tid & 3;       // 0..3   column group
    const int c0   = cg * 16;
    const int lane = tid & 31;
    const int qglob = qb * 64 + r;

    // Q row (this thread's 16 dh-columns) -> registers
    float q[16];
    {
        const float* qp = qkv + ((size_t)(b * SEQ + qglob)) * (3 * C_) + h * DH_ + c0;
#pragma unroll
        for (int j = 0; j < 16; j += 4) {
            float4 v = *(const float4*)(qp + j);
            q[j] = v.x; q[j + 1] = v.y; q[j + 2] = v.z; q[j + 3] = v.w;
        }
    }

    float o[16];
#pragma unroll
    for (int j = 0; j < 16; ++j) o[j] = 0.f;
    float m = -1e30f, l = 0.f;

    for (int kb = 0; kb <= qb; ++kb) {
        __syncthreads();   // protect prior iteration's KsT/Vs reads
        {
            const float* kp =
                qkv + ((size_t)(b * SEQ + kb * 64 + r)) * (3 * C_) + C_ + h * DH_ + c0;
            const float* vp = kp + C_;
#pragma unroll
            for (int j = 0; j < 16; j += 4) {
                float4 kv = *(const float4*)(kp + j);
                KsT[c0 + j + 0][r] = kv.x;
                KsT[c0 + j + 1][r] = kv.y;
                KsT[c0 + j + 2][r] = kv.z;
                KsT[c0 + j + 3][r] = kv.w;
                *(float4*)&Vs[r][c0 + j] = *(const float4*)(vp + j);
            }
        }
        __syncthreads();

        // S = Q K^T for this thread's 16 keys (kb*64 + c0 .. +16)
        float s[16];
#pragma unroll
        for (int j = 0; j < 16; ++j) s[j] = 0.f;
#pragma unroll
        for (int dg = 0; dg < 4; ++dg) {
#pragma unroll
            for (int jj = 0; jj < 16; ++jj) {
                const float qv = __shfl_sync(0xffffffffu, q[jj], (lane & ~3) | dg);
                const int d = dg * 16 + jj;
#pragma unroll
                for (int j = 0; j < 16; j += 4) {
                    float4 kv = *(const float4*)&KsT[d][c0 + j];
                    s[j]     = fmaf(qv, kv.x, s[j]);
                    s[j + 1] = fmaf(qv, kv.y, s[j + 1]);
                    s[j + 2] = fmaf(qv, kv.z, s[j + 2]);
                    s[j + 3] = fmaf(qv, kv.w, s[j + 3]);
                }
            }
        }

        // scale + causal mask
#pragma unroll
        for (int j = 0; j < 16; ++j) {
            const int kg = kb * 64 + c0 + j;
            s[j] = (kg <= qglob) ? s[j] * 0.125f : -1e30f;
        }

        // row max across 16 local + 4 lanes of the group
        float mx = s[0];
#pragma unroll
        for (int j = 1; j < 16; ++j) mx = fmaxf(mx, s[j]);
        mx = fmaxf(mx, __shfl_xor_sync(0xffffffffu, mx, 1));
        mx = fmaxf(mx, __shfl_xor_sync(0xffffffffu, mx, 2));
        const float newm  = fmaxf(m, mx);
        const float alpha = __expf(m - newm);

        float ls = 0.f;
#pragma unroll
        for (int j = 0; j < 16; ++j) { s[j] = __expf(s[j] - newm); ls += s[j]; }
        ls += __shfl_xor_sync(0xffffffffu, ls, 1);
        ls += __shfl_xor_sync(0xffffffffu, ls, 2);
        l = l * alpha + ls;
        m = newm;
#pragma unroll
        for (int j = 0; j < 16; ++j) o[j] *= alpha;

        // O += P @ V   (P row distributed across the 4-lane group)
#pragma unroll
        for (int kg2 = 0; kg2 < 4; ++kg2) {
#pragma unroll
            for (int jj = 0; jj < 16; ++jj) {
                const float p = __shfl_sync(0xffffffffu, s[jj], (lane & ~3) | kg2);
                const int kk = kg2 * 16 + jj;
#pragma unroll
                for (int j = 0; j < 16; j += 4) {
                    float4 vv = *(const float4*)&Vs[kk][c0 + j];
                    o[j]     = fmaf(p, vv.x, o[j]);
                    o[j + 1] = fmaf(p, vv.y, o[j + 1]);
                    o[j + 2] = fmaf(p, vv.z, o[j + 2]);
                    o[j + 3] = fmaf(p, vv.w, o[j + 3]);
                }
            }
        }
    }

    const float invl = 1.f / l;
    float* op = out + ((size_t)(b * SEQ + qglob)) * C_ + h * DH_ + c0;
#pragma unroll
    for (int j = 0; j < 16; j += 4) {
        float4 v = make_float4(o[j] * invl, o[j + 1] * invl, o[j + 2] * invl, o[j + 3] * invl);
        *(float4*)(op + j) = v;
    }
}

// ---------------------------------------------------------------------------
// ctx = attn_out[:, last, :] @ W_ctx.
// C[64, 262144] = A[64,512] @ B[512, 262144].  Memory-bound on the 512 MB B.
// BN=128 tile of N per CTA; B loads fully-coalesced float4.
// A rows gathered from attn_out (row b*512+511), L2-resident after first touch.
// ---------------------------------------------------------------------------
__global__ __launch_bounds__(256)
void ctx_gemm(const float* __restrict__ attn,
              const float* __restrict__ Bmat,
              float* __restrict__ C)
{
    constexpr int BN = 128, BK = 16, K = 512, N = CTXN;
    __shared__ float As[BK][64];
    __shared__ float Bs[BK][BN];

    const int tid = threadIdx.x;
    const int tm = tid >> 4;         // 0..15 -> 4 rows each
    const int tn = tid & 15;         // 0..15 -> 8 cols each
    const int aRow = tid >> 2;       // 0..63  (batch index)
    const int aCol = (tid & 3) * 4;  // 0..12

    const size_t aBase = ((size_t)aRow * SEQ + (SEQ - 1)) * C_ + aCol;  // last token row
    const size_t bCol0 = (size_t)blockIdx.x * BN;

    float acc[4][8];
#pragma unroll
    for (int i = 0; i < 4; ++i)
#pragma unroll
        for (int j = 0; j < 8; ++j) acc[i][j] = 0.f;

    for (int k0 = 0; k0 < K; k0 += BK) {
        float4 a = *(const float4*)(attn + aBase + k0);
        As[aCol + 0][aRow] = a.x;
        As[aCol + 1][aRow] = a.y;
        As[aCol + 2][aRow] = a.z;
        As[aCol + 3][aRow] = a.w;
#pragma unroll
        for (int sIdx = 0; sIdx < 2; ++sIdx) {
            const int slot = tid + sIdx * 256;
            const int row = slot >> 5;
            const int col = (slot & 31) * 4;
            *(float4*)&Bs[row][col] =
                *(const float4*)(Bmat + (size_t)(k0 + row) * N + bCol0 + col);
        }
        __syncthreads();

#pragma unroll
        for (int k = 0; k < BK; ++k) {
            float rM[4], rN[8];
#pragma unroll
            for (int i = 0; i < 4; ++i) rM[i] = As[k][tm * 4 + i];
#pragma unroll
            for (int j = 0; j < 8; ++j) rN[j] = Bs[k][tn * 8 + j];
#pragma unroll
            for (int i = 0; i < 4; ++i)
#pragma unroll
                for (int j = 0; j < 8; ++j)
                    acc[i][j] = fmaf(rM[i], rN[j], acc[i][j]);
        }
        __syncthreads();
    }

#pragma unroll
    for (int i = 0; i < 4; ++i) {
        const size_t crow = (size_t)(tm * 4 + i) * N + bCol0 + tn * 8;
#pragma unroll
        for (int j = 0; j < 8; j += 4) {
            float4 v = make_float4(acc[i][j], acc[i][j + 1], acc[i][j + 2], acc[i][j + 3]);
            *(float4*)(C + crow + j) = v;
        }
    }
}

// ---------------------------------------------------------------------------
// Launch: 5 kernels chained on the default stream (graph-capturable).
// Output tuple (out, decomposed) written contiguously into d_out.
// ---------------------------------------------------------------------------
extern "C" void kernel_launch(void* const* d_in, const int* in_sizes, int n_in,
                              void* d_out, int out_size)
{
    const float* x      = (const float*)d_in[0];
    const float* prev   = (const float*)d_in[1];
    const float* Wattn  = (const float*)d_in[2];
    const float* Wctx   = (const float*)d_in[3];
    const float* Wproj  = (const float*)d_in[4];
    const float* Wproj2 = (const float*)d_in[5];

    float* out = (float*)d_out;
    float* dec = out + (size_t)out_size / 2;   // decomposed follows out

    float *qkv_p, *attn_p, *ctx_p;
    cudaGetSymbolAddress((void**)&qkv_p, g_qkv);
    cudaGetSymbolAddress((void**)&attn_p, g_attn);
    cudaGetSymbolAddress((void**)&ctx_p, g_ctx);

    // 1. qkv = x @ W_attn            [32768,1536]
    sgemm128<false><<<dim3((3 * C_) / 128, MROWS / 128), 256>>>(
        MROWS, 3 * C_, C_, x, nullptr, Wattn, qkv_p);

    // 2. fused causal attention      -> g_attn [32768,512]
    attn_kernel<<<dim3(SEQ / 64, H_, B_), 256>>>(qkv_p, attn_p);

    // 3. ctx = attn[:, -1, :] @ W_ctx -> g_ctx [32768,512] (== [64,512,512])
    ctx_gemm<<<CTXN / 128, 256>>>(attn_p, Wctx, ctx_p);

    // 4. out = attn @ W_proj
    sgemm128<false><<<dim3(C_ / 128, MROWS / 128), 256>>>(
        MROWS, C_, C_, attn_p, nullptr, Wproj, out);

    // 5. decomposed = (prev + ctx) @ W_proj2
    sgemm128<true><<<dim3(C_ / 128, MROWS / 128), 256>>>(
        MROWS, C_, C_, prev, ctx_p, Wproj2, dec);
}

// round 2
// speedup vs baseline: 1.5017x; 1.5017x over previous
#include <cuda_runtime.h>
#include <cstdint>

// ---------------------------------------------------------------------------
// Problem constants
// ---------------------------------------------------------------------------
static constexpr int B_   = 64;
static constexpr int SEQ  = 512;   // W == BLOCK
static constexpr int C_   = 512;   // n_embd
static constexpr int H_   = 8;
static constexpr int DH_  = 64;
static constexpr int MROWS = B_ * SEQ;        // 32768
static constexpr int CTXN  = SEQ * C_;        // 262144 (W_ctx output width)

// ---------------------------------------------------------------------------
// Scratch (allocation-free: __device__ globals)
// ---------------------------------------------------------------------------
__device__ float g_qkv[(long long)MROWS * 3 * C_];   // [32768, 1536]
__device__ float g_attn[(long long)MROWS * C_];      // [32768, 512]
__device__ float g_ctx[(long long)MROWS * C_];       // [32768, 512]

// ---------------------------------------------------------------------------
// Generic fp32 GEMM: C[M,N] = A[M,K] @ B[K,N], all row-major. (unchanged)
// ---------------------------------------------------------------------------
template <bool FUSE>
__global__ __launch_bounds__(256)
void sgemm128(int M, int N, int K,
              const float* __restrict__ A,
              const float* __restrict__ A2,
              const float* __restrict__ B,
              float* __restrict__ C)
{
    constexpr int BM = 128, BN = 128, BK = 8, TM = 8, TN = 8;
    __shared__ float As[BK][BM];
    __shared__ float Bs[BK][BN];

    const int tid = threadIdx.x;
    const int tx  = tid & 15;
    const int ty  = tid >> 4;

    const int aRow = tid >> 1;
    const int aCol = (tid & 1) * 4;
    const int bRow = tid >> 5;
    const int bCol = (tid & 31) * 4;

    const size_t aBase = (size_t)(blockIdx.y * BM + aRow) * K + aCol;
    const size_t bBase = (size_t)blockIdx.x * BN + bCol;

    float acc[TM][TN];
#pragma unroll
    for (int i = 0; i < TM; ++i)
#pragma unroll
        for (int j = 0; j < TN; ++j) acc[i][j] = 0.f;

    for (int k0 = 0; k0 < K; k0 += BK) {
        float4 a = *(const float4*)(A + aBase + k0);
        if (FUSE) {
            float4 a2 = *(const float4*)(A2 + aBase + k0);
            a.x += a2.x; a.y += a2.y; a.z += a2.z; a.w += a2.w;
        }
        As[aCol + 0][aRow] = a.x;
        As[aCol + 1][aRow] = a.y;
        As[aCol + 2][aRow] = a.z;
        As[aCol + 3][aRow] = a.w;
        *(float4*)&Bs[bRow][bCol] =
            *(const float4*)(B + (size_t)(k0 + bRow) * N + bBase);
        __syncthreads();

#pragma unroll
        for (int k = 0; k < BK; ++k) {
            float rM[TM], rN[TN];
#pragma unroll
            for (int i = 0; i < TM; ++i) rM[i] = As[k][ty * TM + i];
#pragma unroll
            for (int j = 0; j < TN; ++j) rN[j] = Bs[k][tx * TN + j];
#pragma unroll
            for (int i = 0; i < TM; ++i)
#pragma unroll
                for (int j = 0; j < TN; ++j)
                    acc[i][j] = fmaf(rM[i], rN[j], acc[i][j]);
        }
        __syncthreads();
    }

#pragma unroll
    for (int i = 0; i < TM; ++i) {
        const size_t crow =
            (size_t)(blockIdx.y * BM + ty * TM + i) * N + blockIdx.x * BN + tx * TN;
#pragma unroll
        for (int j = 0; j < TN; j += 4) {
            float4 v = make_float4(acc[i][j], acc[i][j + 1], acc[i][j + 2], acc[i][j + 3]);
            *(float4*)(C + crow + j) = v;
        }
    }
}

// ---------------------------------------------------------------------------
// Fused causal attention, v2: shared-memory tiled GEMMs, no shuffles in the
// inner loops.
//
// CTA = (qb: 64 q rows, h, b). 256 threads; thread (ty=tid>>4, tx=tid&15)
// owns a 4x4 tile: q-rows ty*4..+3, "cols" tx*4..+3 (keys for S, dh for PV).
//
// smem (dynamic, 49,408 B):
//   Qs [d][qrow]   64x64   (Q pre-scaled by 1/8, transposed)
//   KP            union of Ks [d][key] 64x64  and  Ps [key][qrow] stride 65
//   Vs [key][d]   64x64
//
// Per k-block: load K (transposed) + V;  S = Qs^T Ks (4x4 microkernel, float4
// LDS); online-softmax (shfl_xor over the 16-lane row group only);  P written
// over the dead K buffer (stride 65 -> no stride-64 bank conflict);  O += P V.
// ---------------------------------------------------------------------------
static constexpr int QS_OFF = 0;       // 4096 floats
static constexpr int KP_OFF = 4096;    // 4160 floats (64*65 for P overlay)
static constexpr int VS_OFF = 8256;    // 4096 floats
static constexpr int ATTN_SMEM_BYTES = (VS_OFF + 4096) * 4;  // 49408

__global__ __launch_bounds__(256)
void attn_kernel(const float* __restrict__ qkv, float* __restrict__ out)
{
    extern __shared__ float sm[];
    float* Qs = sm + QS_OFF;
    float* KP = sm + KP_OFF;
    float* Vs = sm + VS_OFF;

    const int qb = blockIdx.x;   // 0..7
    const int h  = blockIdx.y;   // 0..7
    const int b  = blockIdx.z;   // 0..63

    const int tid = threadIdx.x;
    const int tx  = tid & 15;    // 4 cols each
    const int ty  = tid >> 4;    // 4 rows each

    // loader mapping: row = tid>>2 (0..63), d-segment = (tid&3)*16
    const int lrow = tid >> 2;
    const int dseg = (tid & 3) * 16;

    // ---- load Q tile (transposed, pre-scaled by 1/sqrt(dh) = 1/8) ----
    {
        const float* qp =
            qkv + ((size_t)(b * SEQ + qb * 64 + lrow)) * (3 * C_) + h * DH_ + dseg;
#pragma unroll
        for (int j4 = 0; j4 < 4; ++j4) {
            float4 v = *(const float4*)(qp + j4 * 4);
            const int d = dseg + j4 * 4;
            Qs[(d + 0) * 64 + lrow] = v.x * 0.125f;
            Qs[(d + 1) * 64 + lrow] = v.y * 0.125f;
            Qs[(d + 2) * 64 + lrow] = v.z * 0.125f;
            Qs[(d + 3) * 64 + lrow] = v.w * 0.125f;
        }
    }

    float o[4][4];
#pragma unroll
    for (int i = 0; i < 4; ++i)
#pragma unroll
        for (int j = 0; j < 4; ++j) o[i][j] = 0.f;
    float m[4], l[4];
#pragma unroll
    for (int i = 0; i < 4; ++i) { m[i] = -1e30f; l[i] = 0.f; }

    for (int kb = 0; kb <= qb; ++kb) {
        __syncthreads();   // previous iteration done with KP/Vs (and Qs write on kb=0)
        // ---- load K (transposed) and V ----
        {
            const float* kp =
                qkv + ((size_t)(b * SEQ + kb * 64 + lrow)) * (3 * C_) + C_ + h * DH_ + dseg;
            const float* vp = kp + C_;
#pragma unroll
            for (int j4 = 0; j4 < 4; ++j4) {
                float4 kv = *(const float4*)(kp + j4 * 4);
                const int d = dseg + j4 * 4;
                KP[(d + 0) * 64 + lrow] = kv.x;
                KP[(d + 1) * 64 + lrow] = kv.y;
                KP[(d + 2) * 64 + lrow] = kv.z;
                KP[(d + 3) * 64 + lrow] = kv.w;
                *(float4*)&Vs[lrow * 64 + dseg + j4 * 4] = *(const float4*)(vp + j4 * 4);
            }
        }
        __syncthreads();

        // ---- S = (Q/8) K^T : 4x4 microkernel over d ----
        float s[4][4];
#pragma unroll
        for (int i = 0; i < 4; ++i)
#pragma unroll
            for (int j = 0; j < 4; ++j) s[i][j] = 0.f;
#pragma unroll 8
        for (int d = 0; d < 64; ++d) {
            float4 rq = *(const float4*)&Qs[d * 64 + ty * 4];
            float4 rk = *(const float4*)&KP[d * 64 + tx * 4];
            const float qv[4] = {rq.x, rq.y, rq.z, rq.w};
            const float kv[4] = {rk.x, rk.y, rk.z, rk.w};
#pragma unroll
            for (int i = 0; i < 4; ++i)
#pragma unroll
                for (int j = 0; j < 4; ++j)
                    s[i][j] = fmaf(qv[i], kv[j], s[i][j]);
        }

        // ---- causal mask (diagonal block only) ----
        if (kb == qb) {
#pragma unroll
            for (int i = 0; i < 4; ++i)
#pragma unroll
                for (int j = 0; j < 4; ++j)
                    if (tx * 4 + j > ty * 4 + i) s[i][j] = -1e30f;
        }

        // ---- online softmax (row group = 16 consecutive lanes) ----
        float p[4][4];
#pragma unroll
        for (int i = 0; i < 4; ++i) {
            float mx = fmaxf(fmaxf(s[i][0], s[i][1]), fmaxf(s[i][2], s[i][3]));
            mx = fmaxf(mx, __shfl_xor_sync(0xffffffffu, mx, 1));
            mx = fmaxf(mx, __shfl_xor_sync(0xffffffffu, mx, 2));
            mx = fmaxf(mx, __shfl_xor_sync(0xffffffffu, mx, 4));
            mx = fmaxf(mx, __shfl_xor_sync(0xffffffffu, mx, 8));
            const float newm  = fmaxf(m[i], mx);
            const float alpha = __expf(m[i] - newm);
            float ls = 0.f;
#pragma unroll
            for (int j = 0; j < 4; ++j) {
                p[i][j] = __expf(s[i][j] - newm);
                ls += p[i][j];
            }
            ls += __shfl_xor_sync(0xffffffffu, ls, 1);
            ls += __shfl_xor_sync(0xffffffffu, ls, 2);
            ls += __shfl_xor_sync(0xffffffffu, ls, 4);
            ls += __shfl_xor_sync(0xffffffffu, ls, 8);
            l[i] = l[i] * alpha + ls;
            m[i] = newm;
#pragma unroll
            for (int j = 0; j < 4; ++j) o[i][j] *= alpha;
        }

        __syncthreads();   // all S reads of K done -> safe to overwrite with P
        // ---- write P^T over the dead K buffer (stride 65) ----
#pragma unroll
        for (int i = 0; i < 4; ++i)
#pragma unroll
            for (int j = 0; j < 4; ++j)
                KP[(tx * 4 + j) * 65 + ty * 4 + i] = p[i][j];
        __syncthreads();

        // ---- O += P V ----
#pragma unroll 4
        for (int k = 0; k < 64; ++k) {
            float rp[4];
#pragma unroll
            for (int i = 0; i < 4; ++i) rp[i] = KP[k * 65 + ty * 4 + i];
            float4 rv = *(const float4*)&Vs[k * 64 + tx * 4];
            const float vv[4] = {rv.x, rv.y, rv.z, rv.w};
#pragma unroll
            for (int i = 0; i < 4; ++i)
#pragma unroll
                for (int j = 0; j < 4; ++j)
                    o[i][j] = fmaf(rp[i], vv[j], o[i][j]);
        }
    }

    // ---- normalize + store ----
#pragma unroll
    for (int i = 0; i < 4; ++i) {
        const float invl = 1.f / l[i];
        float* op = out + ((size_t)(b * SEQ + qb * 64 + ty * 4 + i)) * C_ + h * DH_ + tx * 4;
        float4 v = make_float4(o[i][0] * invl, o[i][1] * invl,
                               o[i][2] * invl, o[i][3] * invl);
        *(float4*)op = v;
    }
}

// ---------------------------------------------------------------------------
// ctx = attn_out[:, last, :] @ W_ctx.  (unchanged — HBM-bound)
// ---------------------------------------------------------------------------
__global__ __launch_bounds__(256)
void ctx_gemm(const float* __restrict__ attn,
              const float* __restrict__ Bmat,
              float* __restrict__ C)
{
    constexpr int BN = 128, BK = 16, K = 512, N = CTXN;
    __shared__ float As[BK][64];
    __shared__ float Bs[BK][BN];

    const int tid = threadIdx.x;
    const int tm = tid >> 4;
    const int tn = tid & 15;
    const int aRow = tid >> 2;
    const int aCol = (tid & 3) * 4;

    const size_t aBase = ((size_t)aRow * SEQ + (SEQ - 1)) * C_ + aCol;
    const size_t bCol0 = (size_t)blockIdx.x * BN;

    float acc[4][8];
#pragma unroll
    for (int i = 0; i < 4; ++i)
#pragma unroll
        for (int j = 0; j < 8; ++j) acc[i][j] = 0.f;

    for (int k0 = 0; k0 < K; k0 += BK) {
        float4 a = *(const float4*)(attn + aBase + k0);
        As[aCol + 0][aRow] = a.x;
        As[aCol + 1][aRow] = a.y;
        As[aCol + 2][aRow] = a.z;
        As[aCol + 3][aRow] = a.w;
#pragma unroll
        for (int sIdx = 0; sIdx < 2; ++sIdx) {
            const int slot = tid + sIdx * 256;
            const int row = slot >> 5;
            const int col = (slot & 31) * 4;
            *(float4*)&Bs[row][col] =
                *(const float4*)(Bmat + (size_t)(k0 + row) * N + bCol0 + col);
        }
        __syncthreads();

#pragma unroll
        for (int k = 0; k < BK; ++k) {
            float rM[4], rN[8];
#pragma unroll
            for (int i = 0; i < 4; ++i) rM[i] = As[k][tm * 4 + i];
#pragma unroll
            for (int j = 0; j < 8; ++j) rN[j] = Bs[k][tn * 8 + j];
#pragma unroll
            for (int i = 0; i < 4; ++i)
#pragma unroll
                for (int j = 0; j < 8; ++j)
                    acc[i][j] = fmaf(rM[i], rN[j], acc[i][j]);
        }
        __syncthreads();
    }

#pragma unroll
    for (int i = 0; i < 4; ++i) {
        const size_t crow = (size_t)(tm * 4 + i) * N + bCol0 + tn * 8;
#pragma unroll
        for (int j = 0; j < 8; j += 4) {
            float4 v = make_float4(acc[i][j], acc[i][j + 1], acc[i][j + 2], acc[i][j + 3]);
            *(float4*)(C + crow + j) = v;
        }
    }
}

// ---------------------------------------------------------------------------
// Launch
// ---------------------------------------------------------------------------
extern "C" void kernel_launch(void* const* d_in, const int* in_sizes, int n_in,
                              void* d_out, int out_size)
{
    const float* x      = (const float*)d_in[0];
    const float* prev   = (const float*)d_in[1];
    const float* Wattn  = (const float*)d_in[2];
    const float* Wctx   = (const float*)d_in[3];
    const float* Wproj  = (const float*)d_in[4];
    const float* Wproj2 = (const float*)d_in[5];

    float* out = (float*)d_out;
    float* dec = out + (size_t)out_size / 2;

    float *qkv_p, *attn_p, *ctx_p;
    cudaGetSymbolAddress((void**)&qkv_p, g_qkv);
    cudaGetSymbolAddress((void**)&attn_p, g_attn);
    cudaGetSymbolAddress((void**)&ctx_p, g_ctx);

    // allow >48KB dynamic smem for the attention kernel (idempotent)
    cudaFuncSetAttribute(attn_kernel,
                         cudaFuncAttributeMaxDynamicSharedMemorySize,
                         ATTN_SMEM_BYTES);

    // 1. qkv = x @ W_attn
    sgemm128<false><<<dim3((3 * C_) / 128, MROWS / 128), 256>>>(
        MROWS, 3 * C_, C_, x, nullptr, Wattn, qkv_p);

    // 2. fused causal attention
    attn_kernel<<<dim3(SEQ / 64, H_, B_), 256, ATTN_SMEM_BYTES>>>(qkv_p, attn_p);

    // 3. ctx = attn[:, -1, :] @ W_ctx
    ctx_gemm<<<CTXN / 128, 256>>>(attn_p, Wctx, ctx_p);

    // 4. out = attn @ W_proj
    sgemm128<false><<<dim3(C_ / 128, MROWS / 128), 256>>>(
        MROWS, C_, C_, attn_p, nullptr, Wproj, out);

    // 5. decomposed = (prev + ctx) @ W_proj2
    sgemm128<true><<<dim3(C_ / 128, MROWS / 128), 256>>>(
        MROWS, C_, C_, prev, ctx_p, Wproj2, dec);
}